// round 3
// baseline (speedup 1.0000x reference)
#include <cuda_runtime.h>
#include <math.h>

// Gating: x[B=8,S=8192,H=512] f32, gate_w[E=4,H], gate_b[E]
// Outputs concatenated in d_out (float32):
//   [0, 4T)        sparse_logits  (softmax over top-2, zeros elsewhere)
//   [4T, 6T)       indices (top-2 expert ids, as float)
//   [6T, 10T)      gate_logit (raw logits)
// T = B*S = 65536.

#define HIDDEN 512
#define NEXP 4
#define NTOK 65536

__global__ __launch_bounds__(256) void gating_kernel(
    const float* __restrict__ x,
    const float* __restrict__ gate_w,
    const float* __restrict__ gate_b,
    float* __restrict__ out)
{
    // gate_w staged in shared: 4 experts x 512 floats = 8KB, as float4
    __shared__ float4 sgw[NEXP][HIDDEN / 4];
    __shared__ float sgb[NEXP];

    int tid = threadIdx.x;
    for (int i = tid; i < NEXP * (HIDDEN / 4); i += blockDim.x) {
        ((float4*)sgw)[i] = ((const float4*)gate_w)[i];
    }
    if (tid < NEXP) sgb[tid] = gate_b[tid];
    __syncthreads();

    int gwarp = (blockIdx.x * blockDim.x + tid) >> 5;   // token id
    int lane  = tid & 31;
    if (gwarp >= NTOK) return;

    const float4* xr = (const float4*)(x + (size_t)gwarp * HIDDEN);

    float a0 = 0.f, a1 = 0.f, a2 = 0.f, a3 = 0.f;
#pragma unroll
    for (int i = 0; i < 4; i++) {
        float4 v  = xr[lane + i * 32];
        float4 w0 = sgw[0][lane + i * 32];
        float4 w1 = sgw[1][lane + i * 32];
        float4 w2 = sgw[2][lane + i * 32];
        float4 w3 = sgw[3][lane + i * 32];
        a0 += v.x * w0.x + v.y * w0.y + v.z * w0.z + v.w * w0.w;
        a1 += v.x * w1.x + v.y * w1.y + v.z * w1.z + v.w * w1.w;
        a2 += v.x * w2.x + v.y * w2.y + v.z * w2.z + v.w * w2.w;
        a3 += v.x * w3.x + v.y * w3.y + v.z * w3.z + v.w * w3.w;
    }
#pragma unroll
    for (int o = 16; o > 0; o >>= 1) {
        a0 += __shfl_xor_sync(0xFFFFFFFFu, a0, o);
        a1 += __shfl_xor_sync(0xFFFFFFFFu, a1, o);
        a2 += __shfl_xor_sync(0xFFFFFFFFu, a2, o);
        a3 += __shfl_xor_sync(0xFFFFFFFFu, a3, o);
    }

    if (lane == 0) {
        float l[NEXP];
        l[0] = a0 + sgb[0];
        l[1] = a1 + sgb[1];
        l[2] = a2 + sgb[2];
        l[3] = a3 + sgb[3];

        // gate_logit (raw logits)
        float4* glog = (float4*)(out + (size_t)6 * NTOK);
        glog[gwarp] = make_float4(l[0], l[1], l[2], l[3]);

        // top-2 (stable: earlier index wins ties, matching jax top_k)
        int i0 = 0; float m0 = l[0];
#pragma unroll
        for (int e = 1; e < NEXP; e++) { if (l[e] > m0) { m0 = l[e]; i0 = e; } }
        int i1 = -1; float m1 = -INFINITY;
#pragma unroll
        for (int e = 0; e < NEXP; e++) {
            if (e != i0 && l[e] > m1) { m1 = l[e]; i1 = e; }
        }

        // softmax over {m0, m1} (others are -inf -> 0)
        float e1 = __expf(m1 - m0);
        float inv = 1.0f / (1.0f + e1);
        float p0 = inv;
        float p1 = e1 * inv;

        float sp[NEXP] = {0.f, 0.f, 0.f, 0.f};
        sp[i0] = p0;
        sp[i1] = p1;
        float4* spv = (float4*)out;
        spv[gwarp] = make_float4(sp[0], sp[1], sp[2], sp[3]);

        // indices as float
        float2* idx = (float2*)(out + (size_t)4 * NTOK);
        idx[gwarp] = make_float2((float)i0, (float)i1);
    }
}

extern "C" void kernel_launch(void* const* d_in, const int* in_sizes, int n_in,
                              void* d_out, int out_size)
{
    const float* x      = (const float*)d_in[0];
    const float* gate_w = (const float*)d_in[1];
    const float* gate_b = (const float*)d_in[2];
    float* out = (float*)d_out;

    // 65536 tokens, 1 warp/token, 8 warps/block -> 8192 blocks
    gating_kernel<<<NTOK / 8, 256>>>(x, gate_w, gate_b, out);
}